// round 5
// baseline (speedup 1.0000x reference)
#include <cuda_runtime.h>

#define HW_   1048576   // 1024*1024
#define W_    1024
#define H_    1024
#define NTR_  12

// Output float layout (out_size = 12*4*HW + 144):
//   xs   : [0, 12*3*HW)        (12,3,1024,1024)
//   os   : [12*3*HW, 12*4*HW)  (12,1,1024,1024)
//   z    : [12*4*HW, +72)   inv_z: [+72, +144)

// One block per (row h, transform n). 256 threads; thread handles pixels
// w = p*256 + tid -> lanes contiguous. Interior fast path: warp-uniform,
// no clamps, os==1, and corner10/corner11 reused from neighbor lane via
// shfl_down (predicated LDG fallback only where the neighbor offset breaks).
__global__ void __launch_bounds__(256)
sample_row_kernel(const float* __restrict__ x,
                  const float* __restrict__ A,
                  float* __restrict__ out) {
    const int n   = blockIdx.y;
    const int h   = blockIdx.x;
    const int tid = threadIdx.x;

    const float t00 = __ldg(A + n*6 + 0);
    const float t01 = __ldg(A + n*6 + 1);
    const float t02 = __ldg(A + n*6 + 2);
    const float t10 = __ldg(A + n*6 + 3);
    const float t11 = __ldg(A + n*6 + 4);
    const float t12 = __ldg(A + n*6 + 5);

    // Fold z / inv_z emission into this kernel (block h==0, one thread).
    if (h == 0 && tid == 0) {
        float* z  = out + (size_t)NTR_ * 4 * HW_ + n * 6;
        float* iz = z + NTR_ * 6;
        z[0] = t00; z[1] = t01; z[2] = t02;
        z[3] = t10; z[4] = t11; z[5] = t12;
        float inv = 1.0f / (t00 * t11 - t01 * t10);
        float ia =  t11 * inv, ib = -t01 * inv;
        float ic = -t10 * inv, id =  t00 * inv;
        iz[0] = ia; iz[1] = ib; iz[2] = -(ia * t02 + ib * t12);
        iz[3] = ic; iz[4] = id; iz[5] = -(ic * t02 + id * t12);
    }

    // ix = t00*(w+0.5) + t01*(h+0.5) + cx ; iy likewise
    const float cx = 512.0f * (t02 - t00 - t01 + 1.0f) - 0.5f;
    const float cy = 512.0f * (t12 - t10 - t11 + 1.0f) - 0.5f;
    const float fh = (float)h + 0.5f;
    const float hx = fmaf(t01, fh, cx);
    const float hy = fmaf(t11, fh, cy);

    const size_t row = (size_t)h * W_;
    float* xs0 = out + (size_t)n * 3 * HW_ + row;
    float* xs1 = xs0 + HW_;
    float* xs2 = xs1 + HW_;
    float* oso = out + (size_t)NTR_ * 3 * HW_ + (size_t)n * HW_ + row;

    const int lane_base = tid & ~31;   // warp's first tid (lane-uniform)

    #pragma unroll
    for (int p = 0; p < 4; ++p) {
        const int w = p * 256 + tid;
        const float fw = (float)w + 0.5f;
        const float ix = fmaf(t00, fw, hx);
        const float iy = fmaf(t10, fw, hy);

        const float x0f = floorf(ix);
        const float y0f = floorf(iy);
        const float wx1 = ix - x0f;
        const float wy1 = iy - y0f;
        const float wx0 = 1.0f - wx1;
        const float wy0 = 1.0f - wy1;
        const float w00 = wx0 * wy0;
        const float w10 = wx1 * wy0;
        const float w01 = wx0 * wy1;
        const float w11 = wx1 * wy1;

        const int x0 = (int)x0f, y0 = (int)y0f;

        // ---- warp-uniform interior test (lane-invariant operands) ----
        const float wbA = (float)(p * 256 + lane_base) + 0.5f;
        const float wbB = wbA + 31.0f;
        const float exA = fmaf(t00, wbA, hx), exB = fmaf(t00, wbB, hx);
        const float eyA = fmaf(t10, wbA, hy), eyB = fmaf(t10, wbB, hy);
        const float xlo = fminf(exA, exB), xhi = fmaxf(exA, exB);
        const float ylo = fminf(eyA, eyB), yhi = fmaxf(eyA, eyB);
        const bool interior = (xlo >= 1.0f) & (xhi <= 1021.0f) &
                              (ylo >= 1.0f) & (yhi <= 1021.0f);

        float r0, r1, r2, ro;
        if (interior) {
            const int o = (y0 << 10) + x0;
            const float* s = x + o;

            // Compact diagonal loads: corner00 + corner01, 3 channels.
            float a00 = __ldg(s);             float a01 = __ldg(s + W_);
            float b00 = __ldg(s + HW_);       float b01 = __ldg(s + HW_ + W_);
            float c00 = __ldg(s + 2*HW_);     float c01 = __ldg(s + 2*HW_ + W_);

            // Neighbor-lane reuse: lane i+1's corner00 IS lane i's corner10
            // iff its o equals o+1 (same row, x-step 1). shfl_down on lane 31
            // returns own value -> condition false -> predicated load.
            const int on = __shfl_down_sync(0xFFFFFFFFu, o, 1);
            float a10 = __shfl_down_sync(0xFFFFFFFFu, a00, 1);
            float b10 = __shfl_down_sync(0xFFFFFFFFu, b00, 1);
            float c10 = __shfl_down_sync(0xFFFFFFFFu, c00, 1);
            float a11 = __shfl_down_sync(0xFFFFFFFFu, a01, 1);
            float b11 = __shfl_down_sync(0xFFFFFFFFu, b01, 1);
            float c11 = __shfl_down_sync(0xFFFFFFFFu, c01, 1);

            if (on != o + 1) {   // sparse predicated fallback loads
                a10 = __ldg(s + 1);             a11 = __ldg(s + W_ + 1);
                b10 = __ldg(s + HW_ + 1);       b11 = __ldg(s + HW_ + W_ + 1);
                c10 = __ldg(s + 2*HW_ + 1);     c11 = __ldg(s + 2*HW_ + W_ + 1);
            }

            r0 = a00 * w00 + a10 * w10 + a01 * w01 + a11 * w11;
            r1 = b00 * w00 + b10 * w10 + b01 * w01 + b11 * w11;
            r2 = c00 * w00 + c10 * w10 + c01 * w01 + c11 * w11;
            ro = 1.0f;
        } else {
            const int x1 = x0 + 1, y1 = y0 + 1;
            const bool vx0 = ((unsigned)x0 < (unsigned)W_);
            const bool vx1 = ((unsigned)x1 < (unsigned)W_);
            const bool vy0 = ((unsigned)y0 < (unsigned)H_);
            const bool vy1 = ((unsigned)y1 < (unsigned)H_);

            const float m00 = w00 * (float)(vx0 && vy0);
            const float m10 = w10 * (float)(vx1 && vy0);
            const float m01 = w01 * (float)(vx0 && vy1);
            const float m11 = w11 * (float)(vx1 && vy1);

            const int xc0 = min(max(x0, 0), W_ - 1);
            const int xc1 = min(max(x1, 0), W_ - 1);
            const int yc0 = min(max(y0, 0), H_ - 1);
            const int yc1 = min(max(y1, 0), H_ - 1);

            const int o00 = (yc0 << 10) + xc0;
            const int o10 = (yc0 << 10) + xc1;
            const int o01 = (yc1 << 10) + xc0;
            const int o11 = (yc1 << 10) + xc1;

            r0 = __ldg(x + o00)         * m00 + __ldg(x + o10)         * m10
               + __ldg(x + o01)         * m01 + __ldg(x + o11)         * m11;
            r1 = __ldg(x + HW_ + o00)   * m00 + __ldg(x + HW_ + o10)   * m10
               + __ldg(x + HW_ + o01)   * m01 + __ldg(x + HW_ + o11)   * m11;
            r2 = __ldg(x + 2*HW_ + o00) * m00 + __ldg(x + 2*HW_ + o10) * m10
               + __ldg(x + 2*HW_ + o01) * m01 + __ldg(x + 2*HW_ + o11) * m11;
            ro = m00 + m10 + m01 + m11;
        }

        xs0[w] = r0;
        xs1[w] = r1;
        xs2[w] = r2;
        oso[w] = ro;
    }
}

extern "C" void kernel_launch(void* const* d_in, const int* in_sizes, int n_in,
                              void* d_out, int out_size) {
    const float* x = (const float*)d_in[0];        // (1,3,1024,1024)
    const float* A = (const float*)d_in[1];        // (1,12,2,3)
    float* out = (float*)d_out;

    dim3 grid(H_, NTR_);
    sample_row_kernel<<<grid, 256>>>(x, A, out);
}